// round 11
// baseline (speedup 1.0000x reference)
#include <cuda_runtime.h>
#include <cuda_bf16.h>
#include <cuda_fp16.h>
#include <math.h>
#include <stdint.h>

#define C 128
#define NMAX 50016
#define EMAX 800032
#define AGG_BLOCKS_MAX 6256

// ---------------- static device scratch ----------------
__device__ __align__(16) __half g_xlh[NMAX * C];   // xl in fp16
__device__ float g_ai[NMAX];
__device__ float g_aj[NMAX];
__device__ int   g_deg[NMAX];
__device__ int   g_off[NMAX];
__device__ int   g_cur[NMAX];
__device__ int   g_srcs[EMAX];
__device__ float g_sum[C];
__device__ float g_sumsq[C];
__device__ __align__(16) float g_bnpart[AGG_BLOCKS_MAX * 256];
__device__ int   g_part[512];
__device__ int   g_is64;

__device__ __forceinline__ uint32_t smem_u32(const void* p) {
    uint32_t a;
    asm("{ .reg .u64 t; cvta.to.shared.u64 t, %1; cvt.u32.u64 %0, t; }" : "=r"(a) : "l"(p));
    return a;
}
__device__ __forceinline__ uint32_t pack_bf2(float x, float y) {
    __nv_bfloat162 h(__float2bfloat16_rn(x), __float2bfloat16_rn(y));
    return *reinterpret_cast<uint32_t*>(&h);
}
__device__ __forceinline__ uint32_t pack_lo2(float x, float y, uint32_t hi) {
    __nv_bfloat162 h = *reinterpret_cast<__nv_bfloat162*>(&hi);
    return pack_bf2(x - __bfloat162float(h.x), y - __bfloat162float(h.y));
}
__device__ __forceinline__ void mma_bf16(float* d, const uint32_t* a, uint32_t b0, uint32_t b1) {
    asm volatile(
        "mma.sync.aligned.m16n8k16.row.col.f32.bf16.bf16.f32 "
        "{%0,%1,%2,%3}, {%4,%5,%6,%7}, {%8,%9}, {%0,%1,%2,%3};"
        : "+f"(d[0]), "+f"(d[1]), "+f"(d[2]), "+f"(d[3])
        : "r"(a[0]), "r"(a[1]), "r"(a[2]), "r"(a[3]), "r"(b0), "r"(b1));
}
__device__ __forceinline__ void ldmat4(uint32_t* r, uint32_t addr) {
    asm volatile("ldmatrix.sync.aligned.m8n8.x4.shared.b16 {%0,%1,%2,%3}, [%4];"
        : "=r"(r[0]), "=r"(r[1]), "=r"(r[2]), "=r"(r[3]) : "r"(addr));
}

// ---------------- zero + dtype detect ----------------
__global__ void zero_detect_kernel(const int* __restrict__ ei32, int n) {
    int i = blockIdx.x * blockDim.x + threadIdx.x;
    if (i < n) g_deg[i] = 0;
    if (i < C) { g_sum[i] = 0.f; g_sumsq[i] = 0.f; }
    if (blockIdx.x == 0 && threadIdx.x == 0) {
        int is64 = 1;
        for (int k = 0; k < 64; k++)
            if (ei32[2 * k + 1] != 0) { is64 = 0; break; }
        g_is64 = is64;
    }
}

// ---------------- HMMA GEMM (bf16 split) + fully fused alpha ----------------
__global__ __launch_bounds__(256) void gemm_mma_kernel(
    const float* __restrict__ x, const float* __restrict__ w,
    const float* __restrict__ emb,
    const float* __restrict__ att_i, const float* __restrict__ att_j,
    const float* __restrict__ att_em_i, const float* __restrict__ att_em_j, int n)
{
    extern __shared__ __align__(256) char smem[];
    char* Whi = smem;            // 32KB swizzled
    char* Wlo = smem + 32768;

    int tid  = threadIdx.x;
    int lane = tid & 31;
    int wid  = tid >> 5;
    int rowBase = blockIdx.x * 128;

#pragma unroll
    for (int it = 0; it < 16; it++) {
        int idx = it * 256 + tid;
        int o  = idx >> 5;
        int k4 = idx & 31;
        float4 v = *reinterpret_cast<const float4*>(&w[(size_t)o * C + k4 * 4]);
        uint32_t h0 = pack_bf2(v.x, v.y), h1 = pack_bf2(v.z, v.w);
        uint32_t l0 = pack_lo2(v.x, v.y, h0), l1 = pack_lo2(v.z, v.w, h1);
        uint32_t off = (uint32_t)(o * 256 + ((((k4 >> 1) ^ (o & 7)) << 4) | ((k4 & 1) * 8)));
        *reinterpret_cast<uint2*>(Whi + off) = make_uint2(h0, h1);
        *reinterpret_cast<uint2*>(Wlo + off) = make_uint2(l0, l1);
    }
    __syncthreads();

    uint32_t whi_base = smem_u32(Whi);
    uint32_t wlo_base = smem_u32(Wlo);

    int oLane = ((lane >> 4) & 1) * 8 + (lane & 7);
    int khalf = (lane >> 3) & 1;
    int i7 = lane & 7;

    float acc[16][4];
#pragma unroll
    for (int t = 0; t < 16; t++)
#pragma unroll
        for (int q = 0; q < 4; q++) acc[t][q] = 0.f;

    int r0 = rowBase + wid * 16 + (lane >> 2);
    int r1 = r0 + 8;
    const float2 z2 = make_float2(0.f, 0.f);

    for (int ks = 0; ks < 8; ks++) {
        int k0 = ks * 16 + (lane & 3) * 2;
        float2 v00 = (r0 < n) ? *reinterpret_cast<const float2*>(&x[(size_t)r0 * C + k0])     : z2;
        float2 v02 = (r0 < n) ? *reinterpret_cast<const float2*>(&x[(size_t)r0 * C + k0 + 8]) : z2;
        float2 v10 = (r1 < n) ? *reinterpret_cast<const float2*>(&x[(size_t)r1 * C + k0])     : z2;
        float2 v12 = (r1 < n) ? *reinterpret_cast<const float2*>(&x[(size_t)r1 * C + k0 + 8]) : z2;

        uint32_t ahi[4], alo[4];
        ahi[0] = pack_bf2(v00.x, v00.y); alo[0] = pack_lo2(v00.x, v00.y, ahi[0]);
        ahi[1] = pack_bf2(v10.x, v10.y); alo[1] = pack_lo2(v10.x, v10.y, ahi[1]);
        ahi[2] = pack_bf2(v02.x, v02.y); alo[2] = pack_lo2(v02.x, v02.y, ahi[2]);
        ahi[3] = pack_bf2(v12.x, v12.y); alo[3] = pack_lo2(v12.x, v12.y, ahi[3]);

        int kline = (ks * 16 + khalf * 8) >> 3;
        uint32_t lineOff = (uint32_t)((kline ^ i7) << 4);

#pragma unroll
        for (int ntp = 0; ntp < 8; ntp++) {
            uint32_t off = (uint32_t)((ntp * 16 + oLane) * 256) + lineOff;
            uint32_t bhi[4], blo[4];
            ldmat4(bhi, whi_base + off);
            ldmat4(blo, wlo_base + off);
            mma_bf16(acc[2 * ntp],     ahi, bhi[0], bhi[1]);
            mma_bf16(acc[2 * ntp],     ahi, blo[0], blo[1]);
            mma_bf16(acc[2 * ntp],     alo, bhi[0], bhi[1]);
            mma_bf16(acc[2 * ntp + 1], ahi, bhi[2], bhi[3]);
            mma_bf16(acc[2 * ntp + 1], ahi, blo[2], blo[3]);
            mma_bf16(acc[2 * ntp + 1], alo, bhi[2], bhi[3]);
        }
    }

    float ai0 = 0.f, ai1 = 0.f, aj0 = 0.f, aj1 = 0.f;
#pragma unroll
    for (int nt = 0; nt < 16; nt++) {
        int c0 = nt * 8 + (lane & 3) * 2;
        float2 vi  = __ldg(reinterpret_cast<const float2*>(&att_i[c0]));
        float2 vj  = __ldg(reinterpret_cast<const float2*>(&att_j[c0]));
        float2 vei = __ldg(reinterpret_cast<const float2*>(&att_em_i[c0]));
        float2 vej = __ldg(reinterpret_cast<const float2*>(&att_em_j[c0]));
        float d0 = acc[nt][0], d1 = acc[nt][1], d2 = acc[nt][2], d3 = acc[nt][3];
        ai0 += d0 * vi.x + d1 * vi.y;  aj0 += d0 * vj.x + d1 * vj.y;
        ai1 += d2 * vi.x + d3 * vi.y;  aj1 += d2 * vj.x + d3 * vj.y;
        if (r0 < n) {
            __half2 h01 = __floats2half2_rn(d0, d1);
            *reinterpret_cast<__half2*>(&g_xlh[(size_t)r0 * C + c0]) = h01;
            float2 e0 = __ldg(reinterpret_cast<const float2*>(&emb[(size_t)r0 * C + c0]));
            ai0 += e0.x * vei.x + e0.y * vei.y;
            aj0 += e0.x * vej.x + e0.y * vej.y;
        }
        if (r1 < n) {
            __half2 h23 = __floats2half2_rn(d2, d3);
            *reinterpret_cast<__half2*>(&g_xlh[(size_t)r1 * C + c0]) = h23;
            float2 e1 = __ldg(reinterpret_cast<const float2*>(&emb[(size_t)r1 * C + c0]));
            ai1 += e1.x * vei.x + e1.y * vei.y;
            aj1 += e1.x * vej.x + e1.y * vej.y;
        }
    }
#pragma unroll
    for (int o = 1; o <= 2; o <<= 1) {
        ai0 += __shfl_xor_sync(0xffffffffu, ai0, o);
        ai1 += __shfl_xor_sync(0xffffffffu, ai1, o);
        aj0 += __shfl_xor_sync(0xffffffffu, aj0, o);
        aj1 += __shfl_xor_sync(0xffffffffu, aj1, o);
    }
    if ((lane & 3) == 0) {
        if (r0 < n) { g_ai[r0] = ai0; g_aj[r0] = aj0; }
        if (r1 < n) { g_ai[r1] = ai1; g_aj[r1] = aj1; }
    }
}

// ---------------- CSR build ----------------
__device__ __forceinline__ int edge_val(const void* ei, long long idx) {
    if (g_is64) return (int)((const long long*)ei)[idx];
    return ((const int*)ei)[idx];
}

// 2 edges per thread (independent loads batched by compiler)
__global__ void hist_kernel(const void* __restrict__ ei, int e) {
    int i = (blockIdx.x * blockDim.x + threadIdx.x) * 2;
    if (i < e) {
        int d0 = edge_val(ei, (long long)e + i);
        int d1 = (i + 1 < e) ? edge_val(ei, (long long)e + i + 1) : -1;
        atomicAdd(&g_deg[d0], 1);
        if (d1 >= 0) atomicAdd(&g_deg[d1], 1);
    }
}

__global__ void scan_partial(int n) {
    __shared__ int sm[256];
    int i = blockIdx.x * 256 + threadIdx.x;
    sm[threadIdx.x] = (i < n) ? g_deg[i] : 0;
    __syncthreads();
    for (int s = 128; s > 0; s >>= 1) {
        if (threadIdx.x < s) sm[threadIdx.x] += sm[threadIdx.x + s];
        __syncthreads();
    }
    if (threadIdx.x == 0) g_part[blockIdx.x] = sm[0];
}

// scan_final: warp-shuffle scan + fused top-level prefix (3 barriers)
__global__ void scan_final(int n, int nb) {
    __shared__ int wsum[8];
    __shared__ int woff[8];
    __shared__ int s_base;
    int tid  = threadIdx.x;
    int lane = tid & 31;
    int wrp  = tid >> 5;

    int p = (tid < nb && tid < blockIdx.x) ? g_part[tid] : 0;
#pragma unroll
    for (int o = 16; o; o >>= 1) p += __shfl_xor_sync(0xffffffffu, p, o);
    if (lane == 0) wsum[wrp] = p;

    int i = blockIdx.x * 256 + tid;
    int v = (i < n) ? g_deg[i] : 0;
    int incl = v;
#pragma unroll
    for (int o = 1; o < 32; o <<= 1) {
        int t = __shfl_up_sync(0xffffffffu, incl, o);
        if (lane >= o) incl += t;
    }
    if (lane == 31) woff[wrp] = incl;
    __syncthreads();

    if (tid == 0) {
        int s = 0;
#pragma unroll
        for (int w = 0; w < 8; w++) s += wsum[w];
        s_base = s;
    }
    if (wrp == 0) {
        int ws = (lane < 8) ? woff[lane] : 0;
        int wi = ws;
#pragma unroll
        for (int o = 1; o < 8; o <<= 1) {
            int t = __shfl_up_sync(0xffffffffu, wi, o);
            if (lane >= o) wi += t;
        }
        if (lane < 8) woff[lane] = wi - ws;
    }
    __syncthreads();

    int excl = incl - v + woff[wrp] + s_base;
    if (i < n) { g_off[i] = excl; g_cur[i] = excl; }
}

// 2 edges per thread
__global__ void scatter_kernel(const void* __restrict__ ei, int e) {
    int i = (blockIdx.x * blockDim.x + threadIdx.x) * 2;
    if (i < e) {
        int s0 = edge_val(ei, i);
        int d0 = edge_val(ei, (long long)e + i);
        bool has1 = (i + 1 < e);
        int s1 = has1 ? edge_val(ei, i + 1) : 0;
        int d1 = has1 ? edge_val(ei, (long long)e + i + 1) : -1;
        int p0 = atomicAdd(&g_cur[d0], 1);
        g_srcs[p0] = s0;
        if (d1 >= 0) {
            int p1 = atomicAdd(&g_cur[d1], 1);
            g_srcs[p1] = s1;
        }
    }
}

// ---------------- fused softmax + aggregation + BN block partials ----------------
__global__ __launch_bounds__(256) void agg_kernel(
    const float* __restrict__ bias, float* __restrict__ out, int n)
{
    __shared__ float s_w[8][32];
    __shared__ int   s_s[8][32];
    __shared__ float s_bn[256];     // [0:128) sum, [128:256) sumsq

    int tid  = threadIdx.x;
    int lane = tid & 31;
    int wid  = tid >> 5;
    s_bn[tid] = 0.f;
    __syncthreads();

    int node = blockIdx.x * 8 + wid;
    if (node < n) {
        int start = g_off[node];
        int deg   = g_deg[node];
        float ain = g_ai[node];
        float aself = ain + g_aj[node];
        float las = aself >= 0.f ? aself : 0.2f * aself;

        const uint2* xh = reinterpret_cast<const uint2*>(g_xlh);

        float wself = __expf(las);
        float denom = wself;
        uint2 hv = xh[(size_t)node * 32 + lane];
        float2 p0 = __half22float2(*reinterpret_cast<__half2*>(&hv.x));
        float2 p1 = __half22float2(*reinterpret_cast<__half2*>(&hv.y));
        float4 acc;
        acc.x = wself * p0.x; acc.y = wself * p0.y;
        acc.z = wself * p1.x; acc.w = wself * p1.y;

        for (int base = start; base < start + deg; base += 32) {
            int idx = base + lane;
            bool valid = idx < start + deg;
            int s = valid ? __ldg(&g_srcs[idx]) : 0;
            float wv = 0.f;
            if (valid) {
                float a = ain + __ldg(&g_aj[s]);
                a = (a >= 0.f) ? a : 0.2f * a;
                wv = __expf(a);
            }
            s_w[wid][lane] = wv;
            s_s[wid][lane] = s;
            __syncwarp();
            int nv = min(32, start + deg - base);
#pragma unroll 16
            for (int j = 0; j < nv; j++) {
                float wj = s_w[wid][j];
                int   sj = s_s[wid][j];
                uint2 h = __ldg(&xh[(size_t)sj * 32 + lane]);
                float2 q0 = __half22float2(*reinterpret_cast<__half2*>(&h.x));
                float2 q1 = __half22float2(*reinterpret_cast<__half2*>(&h.y));
                acc.x += wj * q0.x; acc.y += wj * q0.y;
                acc.z += wj * q1.x; acc.w += wj * q1.y;
                denom += wj;
            }
            __syncwarp();
        }

        float inv = 1.f / (denom + 1e-16f);
        float4 b = __ldg(reinterpret_cast<const float4*>(&bias[lane * 4]));
        float4 r;
        r.x = acc.x * inv + b.x; r.y = acc.y * inv + b.y;
        r.z = acc.z * inv + b.z; r.w = acc.w * inv + b.w;
        reinterpret_cast<float4*>(out)[(size_t)node * 32 + lane] = r;

        // BN partials: spread-address smem atomics (lane-distinct, 8-warp contention)
        int c0 = lane * 4;
        atomicAdd(&s_bn[c0],           r.x); atomicAdd(&s_bn[128 + c0],     r.x * r.x);
        atomicAdd(&s_bn[c0 + 1],       r.y); atomicAdd(&s_bn[128 + c0 + 1], r.y * r.y);
        atomicAdd(&s_bn[c0 + 2],       r.z); atomicAdd(&s_bn[128 + c0 + 2], r.z * r.z);
        atomicAdd(&s_bn[c0 + 3],       r.w); atomicAdd(&s_bn[128 + c0 + 3], r.w * r.w);
    }
    __syncthreads();
    g_bnpart[(size_t)blockIdx.x * 256 + tid] = s_bn[tid];   // coalesced
}

// ---------------- BN gather: reduce block partials (coalesced) ----------------
__global__ __launch_bounds__(256) void bn_gather(int nblocks) {
    int tid = threadIdx.x;
    float acc = 0.f;
    for (int b = blockIdx.x; b < nblocks; b += gridDim.x)
        acc += g_bnpart[(size_t)b * 256 + tid];
    if (tid < C) atomicAdd(&g_sum[tid], acc);
    else         atomicAdd(&g_sumsq[tid - C], acc);
}

__global__ __launch_bounds__(256) void bn_apply(
    float* __restrict__ out, const float* __restrict__ gamma,
    const float* __restrict__ beta, int n)
{
    __shared__ float s_sc[C], s_sh[C];
    int tid = threadIdx.x;
    if (tid < C) {
        float invn = 1.f / (float)n;
        float mu = g_sum[tid] * invn;
        float var = g_sumsq[tid] * invn - mu * mu;
        var = fmaxf(var, 0.f);
        float rstd = rsqrtf(var + 1e-5f);
        float sc = rstd * gamma[tid];
        s_sc[tid] = sc;
        s_sh[tid] = beta[tid] - mu * sc;
    }
    __syncthreads();
    int i = blockIdx.x * blockDim.x + tid;
    if (i < n * 32) {
        int c0 = (i & 31) * 4;
        float4 v = reinterpret_cast<float4*>(out)[i];
        v.x = v.x * s_sc[c0]     + s_sh[c0];
        v.y = v.y * s_sc[c0 + 1] + s_sh[c0 + 1];
        v.z = v.z * s_sc[c0 + 2] + s_sh[c0 + 2];
        v.w = v.w * s_sc[c0 + 3] + s_sh[c0 + 3];
        reinterpret_cast<float4*>(out)[i] = v;
    }
}

// ---------------- stream fork/join ----------------
static cudaStream_t g_s2;
static cudaEvent_t  g_ev1, g_ev2;
static int g_streams_ok = []() {
    if (cudaStreamCreateWithFlags(&g_s2, cudaStreamNonBlocking) != cudaSuccess) return 0;
    if (cudaEventCreateWithFlags(&g_ev1, cudaEventDisableTiming) != cudaSuccess) return 0;
    if (cudaEventCreateWithFlags(&g_ev2, cudaEventDisableTiming) != cudaSuccess) return 0;
    return 1;
}();

#define GEMM_SMEM 65536

extern "C" void kernel_launch(void* const* d_in, const int* in_sizes, int n_in,
                              void* d_out, int out_size)
{
    const float* x        = (const float*)d_in[0];
    const void*  ei       = d_in[1];
    const float* emb      = (const float*)d_in[2];
    const float* lin_w    = (const float*)d_in[3];
    const float* att_i    = (const float*)d_in[4];
    const float* att_j    = (const float*)d_in[5];
    const float* att_em_i = (const float*)d_in[6];
    const float* att_em_j = (const float*)d_in[7];
    const float* bias     = (const float*)d_in[8];
    const float* gamma    = (const float*)d_in[9];
    const float* beta     = (const float*)d_in[10];
    float* out = (float*)d_out;

    int n = in_sizes[0] / C;
    int e = in_sizes[1] / 2;
    int nb = (n + 255) / 256;
    int nAggBlocks = (n + 7) / 8;
    int ePairs = (e + 1) / 2;

    static int smem_set = 0;
    if (!smem_set) {
        cudaFuncSetAttribute(gemm_mma_kernel,
                             cudaFuncAttributeMaxDynamicSharedMemorySize, GEMM_SMEM);
        smem_set = 1;
    }

    if (g_streams_ok) {
        cudaEventRecord(g_ev1, 0);
        cudaStreamWaitEvent(g_s2, g_ev1, 0);
        zero_detect_kernel<<<(n + 255) / 256, 256, 0, g_s2>>>((const int*)ei, n);
        hist_kernel<<<(ePairs + 255) / 256, 256, 0, g_s2>>>(ei, e);
        scan_partial<<<nb, 256, 0, g_s2>>>(n);
        scan_final<<<nb, 256, 0, g_s2>>>(n, nb);
        scatter_kernel<<<(ePairs + 255) / 256, 256, 0, g_s2>>>(ei, e);
        cudaEventRecord(g_ev2, g_s2);
        gemm_mma_kernel<<<(n + 127) / 128, 256, GEMM_SMEM>>>(
            x, lin_w, emb, att_i, att_j, att_em_i, att_em_j, n);
        cudaStreamWaitEvent(0, g_ev2, 0);
    } else {
        zero_detect_kernel<<<(n + 255) / 256, 256>>>((const int*)ei, n);
        gemm_mma_kernel<<<(n + 127) / 128, 256, GEMM_SMEM>>>(
            x, lin_w, emb, att_i, att_j, att_em_i, att_em_j, n);
        hist_kernel<<<(ePairs + 255) / 256, 256>>>(ei, e);
        scan_partial<<<nb, 256>>>(n);
        scan_final<<<nb, 256>>>(n, nb);
        scatter_kernel<<<(ePairs + 255) / 256, 256>>>(ei, e);
    }

    agg_kernel<<<nAggBlocks, 256>>>(bias, out, n);
    bn_gather<<<128, 256>>>(nAggBlocks);
    bn_apply<<<(n * 32 + 255) / 256, 256>>>(out, gamma, beta, n);
}

// round 12
// speedup vs baseline: 1.2487x; 1.2487x over previous
#include <cuda_runtime.h>
#include <cuda_bf16.h>
#include <cuda_fp16.h>
#include <math.h>
#include <stdint.h>

#define C 128
#define NMAX 50016
#define EMAX 800032

// ---------------- static device scratch ----------------
__device__ __align__(16) __half g_xlh[NMAX * C];   // xl in fp16
__device__ float g_ai[NMAX];
__device__ float g_aj[NMAX];
__device__ int   g_deg[NMAX];
__device__ int   g_off[NMAX];
__device__ int   g_cur[NMAX];
__device__ int   g_srcs[EMAX];
__device__ float g_sum[C];
__device__ float g_sumsq[C];
__device__ int   g_part[512];
__device__ int   g_is64;

__device__ __forceinline__ uint32_t smem_u32(const void* p) {
    uint32_t a;
    asm("{ .reg .u64 t; cvta.to.shared.u64 t, %1; cvt.u32.u64 %0, t; }" : "=r"(a) : "l"(p));
    return a;
}
__device__ __forceinline__ uint32_t pack_bf2(float x, float y) {
    __nv_bfloat162 h(__float2bfloat16_rn(x), __float2bfloat16_rn(y));
    return *reinterpret_cast<uint32_t*>(&h);
}
__device__ __forceinline__ uint32_t pack_lo2(float x, float y, uint32_t hi) {
    __nv_bfloat162 h = *reinterpret_cast<__nv_bfloat162*>(&hi);
    return pack_bf2(x - __bfloat162float(h.x), y - __bfloat162float(h.y));
}
__device__ __forceinline__ void mma_bf16(float* d, const uint32_t* a, uint32_t b0, uint32_t b1) {
    asm volatile(
        "mma.sync.aligned.m16n8k16.row.col.f32.bf16.bf16.f32 "
        "{%0,%1,%2,%3}, {%4,%5,%6,%7}, {%8,%9}, {%0,%1,%2,%3};"
        : "+f"(d[0]), "+f"(d[1]), "+f"(d[2]), "+f"(d[3])
        : "r"(a[0]), "r"(a[1]), "r"(a[2]), "r"(a[3]), "r"(b0), "r"(b1));
}
__device__ __forceinline__ void ldmat4(uint32_t* r, uint32_t addr) {
    asm volatile("ldmatrix.sync.aligned.m8n8.x4.shared.b16 {%0,%1,%2,%3}, [%4];"
        : "=r"(r[0]), "=r"(r[1]), "=r"(r[2]), "=r"(r[3]) : "r"(addr));
}

// ---------------- zero + dtype detect ----------------
__global__ void zero_detect_kernel(const int* __restrict__ ei32, int n) {
    int i = blockIdx.x * blockDim.x + threadIdx.x;
    if (i < n) g_deg[i] = 0;
    if (i < C) { g_sum[i] = 0.f; g_sumsq[i] = 0.f; }
    if (blockIdx.x == 0 && threadIdx.x == 0) {
        int is64 = 1;
        for (int k = 0; k < 64; k++)
            if (ei32[2 * k + 1] != 0) { is64 = 0; break; }
        g_is64 = is64;
    }
}

// ---------------- HMMA GEMM (bf16 split) + fully fused alpha ----------------
__global__ __launch_bounds__(256) void gemm_mma_kernel(
    const float* __restrict__ x, const float* __restrict__ w,
    const float* __restrict__ emb,
    const float* __restrict__ att_i, const float* __restrict__ att_j,
    const float* __restrict__ att_em_i, const float* __restrict__ att_em_j, int n)
{
    extern __shared__ __align__(256) char smem[];
    char* Whi = smem;            // 32KB swizzled
    char* Wlo = smem + 32768;

    int tid  = threadIdx.x;
    int lane = tid & 31;
    int wid  = tid >> 5;
    int rowBase = blockIdx.x * 128;

#pragma unroll
    for (int it = 0; it < 16; it++) {
        int idx = it * 256 + tid;
        int o  = idx >> 5;
        int k4 = idx & 31;
        float4 v = *reinterpret_cast<const float4*>(&w[(size_t)o * C + k4 * 4]);
        uint32_t h0 = pack_bf2(v.x, v.y), h1 = pack_bf2(v.z, v.w);
        uint32_t l0 = pack_lo2(v.x, v.y, h0), l1 = pack_lo2(v.z, v.w, h1);
        uint32_t off = (uint32_t)(o * 256 + ((((k4 >> 1) ^ (o & 7)) << 4) | ((k4 & 1) * 8)));
        *reinterpret_cast<uint2*>(Whi + off) = make_uint2(h0, h1);
        *reinterpret_cast<uint2*>(Wlo + off) = make_uint2(l0, l1);
    }
    __syncthreads();

    uint32_t whi_base = smem_u32(Whi);
    uint32_t wlo_base = smem_u32(Wlo);

    int oLane = ((lane >> 4) & 1) * 8 + (lane & 7);
    int khalf = (lane >> 3) & 1;
    int i7 = lane & 7;

    float acc[16][4];
#pragma unroll
    for (int t = 0; t < 16; t++)
#pragma unroll
        for (int q = 0; q < 4; q++) acc[t][q] = 0.f;

    int r0 = rowBase + wid * 16 + (lane >> 2);
    int r1 = r0 + 8;
    const float2 z2 = make_float2(0.f, 0.f);

    for (int ks = 0; ks < 8; ks++) {
        int k0 = ks * 16 + (lane & 3) * 2;
        float2 v00 = (r0 < n) ? *reinterpret_cast<const float2*>(&x[(size_t)r0 * C + k0])     : z2;
        float2 v02 = (r0 < n) ? *reinterpret_cast<const float2*>(&x[(size_t)r0 * C + k0 + 8]) : z2;
        float2 v10 = (r1 < n) ? *reinterpret_cast<const float2*>(&x[(size_t)r1 * C + k0])     : z2;
        float2 v12 = (r1 < n) ? *reinterpret_cast<const float2*>(&x[(size_t)r1 * C + k0 + 8]) : z2;

        uint32_t ahi[4], alo[4];
        ahi[0] = pack_bf2(v00.x, v00.y); alo[0] = pack_lo2(v00.x, v00.y, ahi[0]);
        ahi[1] = pack_bf2(v10.x, v10.y); alo[1] = pack_lo2(v10.x, v10.y, ahi[1]);
        ahi[2] = pack_bf2(v02.x, v02.y); alo[2] = pack_lo2(v02.x, v02.y, ahi[2]);
        ahi[3] = pack_bf2(v12.x, v12.y); alo[3] = pack_lo2(v12.x, v12.y, ahi[3]);

        int kline = (ks * 16 + khalf * 8) >> 3;
        uint32_t lineOff = (uint32_t)((kline ^ i7) << 4);

#pragma unroll
        for (int ntp = 0; ntp < 8; ntp++) {
            uint32_t off = (uint32_t)((ntp * 16 + oLane) * 256) + lineOff;
            uint32_t bhi[4], blo[4];
            ldmat4(bhi, whi_base + off);
            ldmat4(blo, wlo_base + off);
            mma_bf16(acc[2 * ntp],     ahi, bhi[0], bhi[1]);
            mma_bf16(acc[2 * ntp],     ahi, blo[0], blo[1]);
            mma_bf16(acc[2 * ntp],     alo, bhi[0], bhi[1]);
            mma_bf16(acc[2 * ntp + 1], ahi, bhi[2], bhi[3]);
            mma_bf16(acc[2 * ntp + 1], ahi, blo[2], blo[3]);
            mma_bf16(acc[2 * ntp + 1], alo, bhi[2], bhi[3]);
        }
    }

    float ai0 = 0.f, ai1 = 0.f, aj0 = 0.f, aj1 = 0.f;
#pragma unroll
    for (int nt = 0; nt < 16; nt++) {
        int c0 = nt * 8 + (lane & 3) * 2;
        float2 vi  = __ldg(reinterpret_cast<const float2*>(&att_i[c0]));
        float2 vj  = __ldg(reinterpret_cast<const float2*>(&att_j[c0]));
        float2 vei = __ldg(reinterpret_cast<const float2*>(&att_em_i[c0]));
        float2 vej = __ldg(reinterpret_cast<const float2*>(&att_em_j[c0]));
        float d0 = acc[nt][0], d1 = acc[nt][1], d2 = acc[nt][2], d3 = acc[nt][3];
        ai0 += d0 * vi.x + d1 * vi.y;  aj0 += d0 * vj.x + d1 * vj.y;
        ai1 += d2 * vi.x + d3 * vi.y;  aj1 += d2 * vj.x + d3 * vj.y;
        if (r0 < n) {
            __half2 h01 = __floats2half2_rn(d0, d1);
            *reinterpret_cast<__half2*>(&g_xlh[(size_t)r0 * C + c0]) = h01;
            float2 e0 = __ldg(reinterpret_cast<const float2*>(&emb[(size_t)r0 * C + c0]));
            ai0 += e0.x * vei.x + e0.y * vei.y;
            aj0 += e0.x * vej.x + e0.y * vej.y;
        }
        if (r1 < n) {
            __half2 h23 = __floats2half2_rn(d2, d3);
            *reinterpret_cast<__half2*>(&g_xlh[(size_t)r1 * C + c0]) = h23;
            float2 e1 = __ldg(reinterpret_cast<const float2*>(&emb[(size_t)r1 * C + c0]));
            ai1 += e1.x * vei.x + e1.y * vei.y;
            aj1 += e1.x * vej.x + e1.y * vej.y;
        }
    }
#pragma unroll
    for (int o = 1; o <= 2; o <<= 1) {
        ai0 += __shfl_xor_sync(0xffffffffu, ai0, o);
        ai1 += __shfl_xor_sync(0xffffffffu, ai1, o);
        aj0 += __shfl_xor_sync(0xffffffffu, aj0, o);
        aj1 += __shfl_xor_sync(0xffffffffu, aj1, o);
    }
    if ((lane & 3) == 0) {
        if (r0 < n) { g_ai[r0] = ai0; g_aj[r0] = aj0; }
        if (r1 < n) { g_ai[r1] = ai1; g_aj[r1] = aj1; }
    }
}

// ---------------- CSR build ----------------
__device__ __forceinline__ int edge_val(const void* ei, long long idx) {
    if (g_is64) return (int)((const long long*)ei)[idx];
    return ((const int*)ei)[idx];
}

// 2 edges per thread
__global__ void hist_kernel(const void* __restrict__ ei, int e) {
    int i = (blockIdx.x * blockDim.x + threadIdx.x) * 2;
    if (i < e) {
        int d0 = edge_val(ei, (long long)e + i);
        int d1 = (i + 1 < e) ? edge_val(ei, (long long)e + i + 1) : -1;
        atomicAdd(&g_deg[d0], 1);
        if (d1 >= 0) atomicAdd(&g_deg[d1], 1);
    }
}

__global__ void scan_partial(int n) {
    __shared__ int sm[256];
    int i = blockIdx.x * 256 + threadIdx.x;
    sm[threadIdx.x] = (i < n) ? g_deg[i] : 0;
    __syncthreads();
    for (int s = 128; s > 0; s >>= 1) {
        if (threadIdx.x < s) sm[threadIdx.x] += sm[threadIdx.x + s];
        __syncthreads();
    }
    if (threadIdx.x == 0) g_part[blockIdx.x] = sm[0];
}

// scan_final: warp-shuffle scan + fused top-level prefix (3 barriers)
__global__ void scan_final(int n, int nb) {
    __shared__ int wsum[8];
    __shared__ int woff[8];
    __shared__ int s_base;
    int tid  = threadIdx.x;
    int lane = tid & 31;
    int wrp  = tid >> 5;

    int p = (tid < nb && tid < blockIdx.x) ? g_part[tid] : 0;
#pragma unroll
    for (int o = 16; o; o >>= 1) p += __shfl_xor_sync(0xffffffffu, p, o);
    if (lane == 0) wsum[wrp] = p;

    int i = blockIdx.x * 256 + tid;
    int v = (i < n) ? g_deg[i] : 0;
    int incl = v;
#pragma unroll
    for (int o = 1; o < 32; o <<= 1) {
        int t = __shfl_up_sync(0xffffffffu, incl, o);
        if (lane >= o) incl += t;
    }
    if (lane == 31) woff[wrp] = incl;
    __syncthreads();

    if (tid == 0) {
        int s = 0;
#pragma unroll
        for (int w = 0; w < 8; w++) s += wsum[w];
        s_base = s;
    }
    if (wrp == 0) {
        int ws = (lane < 8) ? woff[lane] : 0;
        int wi = ws;
#pragma unroll
        for (int o = 1; o < 8; o <<= 1) {
            int t = __shfl_up_sync(0xffffffffu, wi, o);
            if (lane >= o) wi += t;
        }
        if (lane < 8) woff[lane] = wi - ws;
    }
    __syncthreads();

    int excl = incl - v + woff[wrp] + s_base;
    if (i < n) { g_off[i] = excl; g_cur[i] = excl; }
}

// 2 edges per thread
__global__ void scatter_kernel(const void* __restrict__ ei, int e) {
    int i = (blockIdx.x * blockDim.x + threadIdx.x) * 2;
    if (i < e) {
        int s0 = edge_val(ei, i);
        int d0 = edge_val(ei, (long long)e + i);
        bool has1 = (i + 1 < e);
        int s1 = has1 ? edge_val(ei, i + 1) : 0;
        int d1 = has1 ? edge_val(ei, (long long)e + i + 1) : -1;
        int p0 = atomicAdd(&g_cur[d0], 1);
        g_srcs[p0] = s0;
        if (d1 >= 0) {
            int p1 = atomicAdd(&g_cur[d1], 1);
            g_srcs[p1] = s1;
        }
    }
}

// ---------------- fused softmax + aggregation (R10 shape: warp-uniform, unroll 8) ----------------
__global__ __launch_bounds__(256) void agg_kernel(
    const float* __restrict__ bias, float* __restrict__ out, int n)
{
    __shared__ float s_w[8][32];
    __shared__ int   s_s[8][32];

    int lane = threadIdx.x & 31;
    int wid  = threadIdx.x >> 5;
    int node = blockIdx.x * 8 + wid;
    if (node >= n) return;

    int start = g_off[node];
    int deg   = g_deg[node];
    float ain = g_ai[node];
    float aself = ain + g_aj[node];
    float las = aself >= 0.f ? aself : 0.2f * aself;

    const uint2* xh = reinterpret_cast<const uint2*>(g_xlh);  // 4 halves per uint2

    float wself = __expf(las);
    float denom = wself;
    uint2 hv = xh[(size_t)node * 32 + lane];
    float2 p0 = __half22float2(*reinterpret_cast<__half2*>(&hv.x));
    float2 p1 = __half22float2(*reinterpret_cast<__half2*>(&hv.y));
    float4 acc;
    acc.x = wself * p0.x; acc.y = wself * p0.y;
    acc.z = wself * p1.x; acc.w = wself * p1.y;

    for (int base = start; base < start + deg; base += 32) {
        int idx = base + lane;
        bool valid = idx < start + deg;
        int s = valid ? __ldg(&g_srcs[idx]) : 0;
        float wv = 0.f;
        if (valid) {
            float a = ain + __ldg(&g_aj[s]);
            a = (a >= 0.f) ? a : 0.2f * a;
            wv = __expf(a);
        }
        s_w[wid][lane] = wv;
        s_s[wid][lane] = s;
        __syncwarp();
        int nv = min(32, start + deg - base);
#pragma unroll 8
        for (int j = 0; j < nv; j++) {
            float wj = s_w[wid][j];
            int   sj = s_s[wid][j];
            uint2 h = __ldg(&xh[(size_t)sj * 32 + lane]);
            float2 q0 = __half22float2(*reinterpret_cast<__half2*>(&h.x));
            float2 q1 = __half22float2(*reinterpret_cast<__half2*>(&h.y));
            acc.x += wj * q0.x; acc.y += wj * q0.y;
            acc.z += wj * q1.x; acc.w += wj * q1.y;
            denom += wj;
        }
        __syncwarp();
    }

    float inv = 1.f / (denom + 1e-16f);
    float4 b = __ldg(reinterpret_cast<const float4*>(&bias[lane * 4]));
    float4 r;
    r.x = acc.x * inv + b.x; r.y = acc.y * inv + b.y;
    r.z = acc.z * inv + b.z; r.w = acc.w * inv + b.w;
    reinterpret_cast<float4*>(out)[(size_t)node * 32 + lane] = r;
}

// ---------------- BatchNorm ----------------
__global__ __launch_bounds__(128) void bn_reduce(const float* __restrict__ out, int n) {
    int t = threadIdx.x;
    int r0 = blockIdx.x * 64;
    float s = 0.f, s2 = 0.f;
#pragma unroll 4
    for (int j = 0; j < 64; j++) {
        int r = r0 + j;
        if (r < n) {
            float v = out[r * C + t];
            s += v; s2 += v * v;
        }
    }
    atomicAdd(&g_sum[t], s);
    atomicAdd(&g_sumsq[t], s2);
}

__global__ __launch_bounds__(256) void bn_apply(
    float* __restrict__ out, const float* __restrict__ gamma,
    const float* __restrict__ beta, int n)
{
    __shared__ float s_sc[C], s_sh[C];
    int tid = threadIdx.x;
    if (tid < C) {
        float invn = 1.f / (float)n;
        float mu = g_sum[tid] * invn;
        float var = g_sumsq[tid] * invn - mu * mu;
        var = fmaxf(var, 0.f);
        float rstd = rsqrtf(var + 1e-5f);
        float sc = rstd * gamma[tid];
        s_sc[tid] = sc;
        s_sh[tid] = beta[tid] - mu * sc;
    }
    __syncthreads();
    int i = blockIdx.x * blockDim.x + tid;
    if (i < n * 32) {
        int c0 = (i & 31) * 4;
        float4 v = reinterpret_cast<float4*>(out)[i];
        v.x = v.x * s_sc[c0]     + s_sh[c0];
        v.y = v.y * s_sc[c0 + 1] + s_sh[c0 + 1];
        v.z = v.z * s_sc[c0 + 2] + s_sh[c0 + 2];
        v.w = v.w * s_sc[c0 + 3] + s_sh[c0 + 3];
        reinterpret_cast<float4*>(out)[i] = v;
    }
}

// ---------------- stream fork/join ----------------
static cudaStream_t g_s2;
static cudaEvent_t  g_ev1, g_ev2;
static int g_streams_ok = []() {
    if (cudaStreamCreateWithFlags(&g_s2, cudaStreamNonBlocking) != cudaSuccess) return 0;
    if (cudaEventCreateWithFlags(&g_ev1, cudaEventDisableTiming) != cudaSuccess) return 0;
    if (cudaEventCreateWithFlags(&g_ev2, cudaEventDisableTiming) != cudaSuccess) return 0;
    return 1;
}();

#define GEMM_SMEM 65536

extern "C" void kernel_launch(void* const* d_in, const int* in_sizes, int n_in,
                              void* d_out, int out_size)
{
    const float* x        = (const float*)d_in[0];
    const void*  ei       = d_in[1];
    const float* emb      = (const float*)d_in[2];
    const float* lin_w    = (const float*)d_in[3];
    const float* att_i    = (const float*)d_in[4];
    const float* att_j    = (const float*)d_in[5];
    const float* att_em_i = (const float*)d_in[6];
    const float* att_em_j = (const float*)d_in[7];
    const float* bias     = (const float*)d_in[8];
    const float* gamma    = (const float*)d_in[9];
    const float* beta     = (const float*)d_in[10];
    float* out = (float*)d_out;

    int n = in_sizes[0] / C;
    int e = in_sizes[1] / 2;
    int nb = (n + 255) / 256;
    int ePairs = (e + 1) / 2;

    static int smem_set = 0;
    if (!smem_set) {
        cudaFuncSetAttribute(gemm_mma_kernel,
                             cudaFuncAttributeMaxDynamicSharedMemorySize, GEMM_SMEM);
        smem_set = 1;
    }

    if (g_streams_ok) {
        cudaEventRecord(g_ev1, 0);
        cudaStreamWaitEvent(g_s2, g_ev1, 0);
        zero_detect_kernel<<<(n + 255) / 256, 256, 0, g_s2>>>((const int*)ei, n);
        hist_kernel<<<(ePairs + 255) / 256, 256, 0, g_s2>>>(ei, e);
        scan_partial<<<nb, 256, 0, g_s2>>>(n);
        scan_final<<<nb, 256, 0, g_s2>>>(n, nb);
        scatter_kernel<<<(ePairs + 255) / 256, 256, 0, g_s2>>>(ei, e);
        cudaEventRecord(g_ev2, g_s2);
        gemm_mma_kernel<<<(n + 127) / 128, 256, GEMM_SMEM>>>(
            x, lin_w, emb, att_i, att_j, att_em_i, att_em_j, n);
        cudaStreamWaitEvent(0, g_ev2, 0);
    } else {
        zero_detect_kernel<<<(n + 255) / 256, 256>>>((const int*)ei, n);
        gemm_mma_kernel<<<(n + 127) / 128, 256, GEMM_SMEM>>>(
            x, lin_w, emb, att_i, att_j, att_em_i, att_em_j, n);
        hist_kernel<<<(ePairs + 255) / 256, 256>>>(ei, e);
        scan_partial<<<nb, 256>>>(n);
        scan_final<<<nb, 256>>>(n, nb);
        scatter_kernel<<<(ePairs + 255) / 256, 256>>>(ei, e);
    }

    agg_kernel<<<(n + 7) / 8, 256>>>(bias, out, n);
    bn_reduce<<<(n + 63) / 64, 128>>>(out, n);
    bn_apply<<<(n * 32 + 255) / 256, 256>>>(out, gamma, beta, n);
}